// round 6
// baseline (speedup 1.0000x reference)
#include <cuda_runtime.h>

// Gaussian splatting via tile-owned gather (no global atomics on the volume).
// K1 (memset node): zero per-tile counters. K2: per-gaussian param prep +
// bucket scatter (tile = 16^3). K3: one CTA per tile; thread owns an (x,y)
// column of 16 z-voxels in registers; gaussians in batches of 8 with
// transposed smem tables enabling float4 quad-scan; volume written exactly
// once with coalesced float4 stores.

#define NT 16
#define NTILES (NT * NT * NT)          // 4096
#define CAP 192
#define NMAX 65536

__device__ int    d_counts[NTILES];
__device__ int    d_bucket[NTILES * CAP];
__device__ float4 d_params[2 * NMAX];  // [2g]={cx,cy,cz,inv2s2}; [2g+1]={I, mnPack, mxm1Pack, 0}

__global__ void scatter_kernel(const float* __restrict__ centers,
                               const float* __restrict__ sigmas,
                               const float* __restrict__ intensities,
                               int n) {
    int g = blockIdx.x * blockDim.x + threadIdx.x;
    if (g >= n) return;

    float c3[3];
    c3[0] = __ldg(&centers[3 * g + 0]);
    c3[1] = __ldg(&centers[3 * g + 1]);
    c3[2] = __ldg(&centers[3 * g + 2]);
    const float sig   = __ldg(&sigmas[g]);
    const float inten = __ldg(&intensities[g]);

    const float cut    = 3.0f * sig * 255.0f;
    const float inv2s2 = 0.5f / (sig * sig);

    int mn[3], mx[3];
#pragma unroll
    for (int a = 0; a < 3; a++) {
        float cv = c3[a] * 255.0f;
        mn[a] = (int)floorf(fmaxf(cv - cut, 0.0f));
        mx[a] = (int)fminf(floorf(fminf(cv + cut, 255.0f)) + 1.0f, 256.0f);
    }

    unsigned mnp = (unsigned)mn[0] | ((unsigned)mn[1] << 8) | ((unsigned)mn[2] << 16);
    unsigned mxp = (unsigned)(mx[0] - 1) | ((unsigned)(mx[1] - 1) << 8) | ((unsigned)(mx[2] - 1) << 16);

    d_params[2 * g + 0] = make_float4(c3[0], c3[1], c3[2], inv2s2);
    d_params[2 * g + 1] = make_float4(inten, __uint_as_float(mnp), __uint_as_float(mxp), 0.0f);

    const int t0x = mn[0] >> 4, t1x = (mx[0] - 1) >> 4;
    const int t0y = mn[1] >> 4, t1y = (mx[1] - 1) >> 4;
    const int t0z = mn[2] >> 4, t1z = (mx[2] - 1) >> 4;

    for (int tx = t0x; tx <= t1x; tx++)
        for (int ty = t0y; ty <= t1y; ty++)
            for (int tz = t0z; tz <= t1z; tz++) {
                int t = (tx << 8) | (ty << 4) | tz;
                int slot = atomicAdd(&d_counts[t], 1);
                if (slot < CAP) d_bucket[t * CAP + slot] = g;
            }
}

__global__ void __launch_bounds__(256) accum_kernel(float* __restrict__ out) {
    const int t   = blockIdx.x;
    const int tid = threadIdx.x;
    const int ox = ((t >> 8) & 15) << 4;
    const int oy = ((t >> 4) & 15) << 4;
    const int oz = (t & 15) << 4;

    // Transposed tables: one LDS.128 fetches 4 gaussians' weights.
    __shared__ float sh_px[16][8];     // [x within tile][g]
    __shared__ float sh_py[16][8];     // [y within tile][g]
    __shared__ float sh_pz[8][16];     // [g][z]  (intensity folded in)
    __shared__ float sh_stage[16 * 256];

    int cnt = d_counts[t];
    if (cnt > CAP) cnt = CAP;

    float acc[16];
#pragma unroll
    for (int z = 0; z < 16; z++) acc[z] = 0.0f;

    const int xi = tid >> 4;
    const int yi = tid & 15;
    const int bucket_base = t * CAP;

    for (int b = 0; b < cnt; b += 8) {
        const int Gb = min(8, cnt - b);
        __syncthreads();   // previous batch done before table overwrite

        // Build tables: 512 slots (64 per gaussian, 48 used), zero-padded.
        for (int e = tid; e < 512; e += 256) {
            int g = e >> 6, r = e & 63;
            if (r < 48) {
                int a = r >> 4, i = r & 15;
                float v = 0.0f;
                if (g < Gb) {
                    int gid = d_bucket[bucket_base + b + g];
                    float4 p0 = d_params[2 * gid + 0];
                    float4 p1 = d_params[2 * gid + 1];
                    float  c      = (a == 0) ? p0.x : ((a == 1) ? p0.y : p0.z);
                    unsigned mnp = __float_as_uint(p1.y);
                    unsigned mxp = __float_as_uint(p1.z);
                    int mn_a = (int)((mnp >> (8 * a)) & 255u);
                    int mx_a = (int)((mxp >> (8 * a)) & 255u);
                    int o = (a == 0) ? ox : ((a == 1) ? oy : oz);
                    int gi = o + i;
                    if (gi >= mn_a && gi <= mx_a) {
                        float d = (float)gi / 255.0f - c;
                        v = expf(-d * d * p0.w);
                        if (a == 2) v *= p1.x;
                    }
                }
                if (a == 0)      sh_px[i][g] = v;
                else if (a == 1) sh_py[i][g] = v;
                else             sh_pz[g][i] = v;
            }
        }
        __syncthreads();

        // Quad scan: 4 gaussians per LDS.128.
        float4 xq0 = *(const float4*)&sh_px[xi][0];
        float4 xq1 = *(const float4*)&sh_px[xi][4];
        float4 yq0 = *(const float4*)&sh_py[yi][0];
        float4 yq1 = *(const float4*)&sh_py[yi][4];
        float exy[8];
        exy[0] = xq0.x * yq0.x;  exy[1] = xq0.y * yq0.y;
        exy[2] = xq0.z * yq0.z;  exy[3] = xq0.w * yq0.w;
        exy[4] = xq1.x * yq1.x;  exy[5] = xq1.y * yq1.y;
        exy[6] = xq1.z * yq1.z;  exy[7] = xq1.w * yq1.w;

#pragma unroll
        for (int g = 0; g < 8; g++) {
            if (exy[g] != 0.0f) {
                const float4* ez = (const float4*)sh_pz[g];
                float4 e0 = ez[0], e1 = ez[1], e2 = ez[2], e3 = ez[3];
                float w = exy[g];
                acc[0]  = fmaf(w, e0.x, acc[0]);
                acc[1]  = fmaf(w, e0.y, acc[1]);
                acc[2]  = fmaf(w, e0.z, acc[2]);
                acc[3]  = fmaf(w, e0.w, acc[3]);
                acc[4]  = fmaf(w, e1.x, acc[4]);
                acc[5]  = fmaf(w, e1.y, acc[5]);
                acc[6]  = fmaf(w, e1.z, acc[6]);
                acc[7]  = fmaf(w, e1.w, acc[7]);
                acc[8]  = fmaf(w, e2.x, acc[8]);
                acc[9]  = fmaf(w, e2.y, acc[9]);
                acc[10] = fmaf(w, e2.z, acc[10]);
                acc[11] = fmaf(w, e2.w, acc[11]);
                acc[12] = fmaf(w, e3.x, acc[12]);
                acc[13] = fmaf(w, e3.y, acc[13]);
                acc[14] = fmaf(w, e3.z, acc[14]);
                acc[15] = fmaf(w, e3.w, acc[15]);
            }
        }
    }

    // Transposed writeout: coalesced float4 stores.
    __syncthreads();
#pragma unroll
    for (int z = 0; z < 16; z++) sh_stage[z * 256 + tid] = acc[z];
    __syncthreads();

#pragma unroll
    for (int s = 0; s < 4; s++) {
        int idx = s * 256 + tid;
        int f   = idx << 2;
        int c   = f >> 4;
        int z0  = f & 15;
        float4 v;
        v.x = sh_stage[(z0 + 0) * 256 + c];
        v.y = sh_stage[(z0 + 1) * 256 + c];
        v.z = sh_stage[(z0 + 2) * 256 + c];
        v.w = sh_stage[(z0 + 3) * 256 + c];
        int addr = (ox + (c >> 4)) * 65536 + (oy + (c & 15)) * 256 + oz + z0;
        *(float4*)&out[addr] = v;
    }
}

extern "C" void kernel_launch(void* const* d_in, const int* in_sizes, int n_in,
                              void* d_out, int out_size) {
    const float* centers = (const float*)d_in[0];
    const float* sigmas = (const float*)d_in[1];
    const float* intensities = (const float*)d_in[2];
    float* out = (float*)d_out;
    const int n = in_sizes[1];

    void* counts_ptr = nullptr;
    cudaGetSymbolAddress(&counts_ptr, d_counts);
    cudaMemsetAsync(counts_ptr, 0, NTILES * sizeof(int), 0);

    scatter_kernel<<<(n + 255) / 256, 256>>>(centers, sigmas, intensities, n);
    accum_kernel<<<NTILES, 256>>>(out);
}

// round 7
// speedup vs baseline: 1.3014x; 1.3014x over previous
#include <cuda_runtime.h>

// Gaussian splatting via tile-owned gather (no global atomics on the volume).
// memset node: zero per-tile counters. K2: per-gaussian param prep + bucket
// scatter (tile = 16^3). K3: one CTA per tile; all exp tables built ONCE into
// smem (single barrier), then a barrier-free quad-scan (LDS.128 = 4 gaussians)
// accumulates into per-thread z-column registers; volume written exactly once
// with coalesced float4 stores.

#define NT 16
#define NTILES (NT * NT * NT)          // 4096
#define CAP 192
#define NMAX 65536
#define PXS 196                         // padded row stride (floats)

__device__ int    d_counts[NTILES];
__device__ int    d_bucket[NTILES * CAP];
__device__ float4 d_params[2 * NMAX];  // [2g]={cx,cy,cz,inv2s2}; [2g+1]={I, mnPack, mxm1Pack, 0}

__global__ void scatter_kernel(const float* __restrict__ centers,
                               const float* __restrict__ sigmas,
                               const float* __restrict__ intensities,
                               int n) {
    int g = blockIdx.x * blockDim.x + threadIdx.x;
    if (g >= n) return;

    float c3[3];
    c3[0] = __ldg(&centers[3 * g + 0]);
    c3[1] = __ldg(&centers[3 * g + 1]);
    c3[2] = __ldg(&centers[3 * g + 2]);
    const float sig   = __ldg(&sigmas[g]);
    const float inten = __ldg(&intensities[g]);

    const float cut    = 3.0f * sig * 255.0f;
    const float inv2s2 = 0.5f / (sig * sig);

    int mn[3], mx[3];
#pragma unroll
    for (int a = 0; a < 3; a++) {
        float cv = c3[a] * 255.0f;
        mn[a] = (int)floorf(fmaxf(cv - cut, 0.0f));
        mx[a] = (int)fminf(floorf(fminf(cv + cut, 255.0f)) + 1.0f, 256.0f);
    }

    unsigned mnp = (unsigned)mn[0] | ((unsigned)mn[1] << 8) | ((unsigned)mn[2] << 16);
    unsigned mxp = (unsigned)(mx[0] - 1) | ((unsigned)(mx[1] - 1) << 8) | ((unsigned)(mx[2] - 1) << 16);

    d_params[2 * g + 0] = make_float4(c3[0], c3[1], c3[2], inv2s2);
    d_params[2 * g + 1] = make_float4(inten, __uint_as_float(mnp), __uint_as_float(mxp), 0.0f);

    const int t0x = mn[0] >> 4, t1x = (mx[0] - 1) >> 4;
    const int t0y = mn[1] >> 4, t1y = (mx[1] - 1) >> 4;
    const int t0z = mn[2] >> 4, t1z = (mx[2] - 1) >> 4;

    for (int tx = t0x; tx <= t1x; tx++)
        for (int ty = t0y; ty <= t1y; ty++)
            for (int tz = t0z; tz <= t1z; tz++) {
                int t = (tx << 8) | (ty << 4) | tz;
                int slot = atomicAdd(&d_counts[t], 1);
                if (slot < CAP) d_bucket[t * CAP + slot] = g;
            }
}

// Shared buffer layout (floats):
//   par:  [0, 1536)            CAP*2 float4 params                (6144 B)
//   px:   [1536, 4672)         16 rows x PXS                      (12544 B)
//   py:   [4672, 7808)         16 rows x PXS                      (12544 B)
//   pz:   [7808, 10880)        CAP rows x 16                      (12288 B)
//   stage (writeout) aliases [1536, 5632)  (px/py region, dead by then)
#define SM_PAR   0
#define SM_PX    1536
#define SM_PY    4672
#define SM_PZ    7808
#define SM_TOT   10880
#define SM_STAGE 1536

__global__ void __launch_bounds__(256) accum_kernel(float* __restrict__ out) {
    const int t   = blockIdx.x;
    const int tid = threadIdx.x;
    const int ox = ((t >> 8) & 15) << 4;
    const int oy = ((t >> 4) & 15) << 4;
    const int oz = (t & 15) << 4;

    __shared__ __align__(16) float buf[SM_TOT];
    float4* par = (float4*)&buf[SM_PAR];
    float*  px  = &buf[SM_PX];
    float*  py  = &buf[SM_PY];
    float*  pz  = &buf[SM_PZ];

    int cnt = d_counts[t];
    if (cnt > CAP) cnt = CAP;
    const int cnt8 = (cnt + 7) & ~7;
    const int bucket_base = t * CAP;

    // Stage all params coalesced (2 float4 per gaussian).
    for (int i = tid; i < cnt * 2; i += 256) {
        int g = i >> 1, h = i & 1;
        int gid = d_bucket[bucket_base + g];
        par[i] = d_params[2 * gid + h];
    }
    __syncthreads();

    // Build all tables once. 64 slots per gaussian (48 used); pad rows zeroed.
    for (int e = tid; e < cnt8 * 64; e += 256) {
        int r = e & 63;
        if (r >= 48) continue;
        int g = e >> 6;
        int a = r >> 4, i = r & 15;
        float v = 0.0f;
        if (g < cnt) {
            float4 p0 = par[2 * g + 0];
            float4 p1 = par[2 * g + 1];
            float c = (a == 0) ? p0.x : ((a == 1) ? p0.y : p0.z);
            unsigned mnp = __float_as_uint(p1.y);
            unsigned mxp = __float_as_uint(p1.z);
            int mn_a = (int)((mnp >> (8 * a)) & 255u);
            int mx_a = (int)((mxp >> (8 * a)) & 255u);
            int o = (a == 0) ? ox : ((a == 1) ? oy : oz);
            int gi = o + i;
            if (gi >= mn_a && gi <= mx_a) {
                float d = (float)gi / 255.0f - c;
                v = expf(-d * d * p0.w);
                if (a == 2) v *= p1.x;
            }
        }
        if (a == 0)      px[i * PXS + g] = v;
        else if (a == 1) py[i * PXS + g] = v;
        else             pz[g * 16 + i]  = v;
    }
    __syncthreads();

    const int xi = tid >> 4;
    const int yi = tid & 15;
    const float* pxr = px + xi * PXS;
    const float* pyr = py + yi * PXS;

    float acc[16];
#pragma unroll
    for (int z = 0; z < 16; z++) acc[z] = 0.0f;

    // Barrier-free quad scan over the whole list.
    for (int b = 0; b < cnt8; b += 8) {
        float4 xq0 = *(const float4*)(pxr + b);
        float4 xq1 = *(const float4*)(pxr + b + 4);
        float4 yq0 = *(const float4*)(pyr + b);
        float4 yq1 = *(const float4*)(pyr + b + 4);
        float exy[8];
        exy[0] = xq0.x * yq0.x;  exy[1] = xq0.y * yq0.y;
        exy[2] = xq0.z * yq0.z;  exy[3] = xq0.w * yq0.w;
        exy[4] = xq1.x * yq1.x;  exy[5] = xq1.y * yq1.y;
        exy[6] = xq1.z * yq1.z;  exy[7] = xq1.w * yq1.w;

#pragma unroll
        for (int g = 0; g < 8; g++) {
            if (exy[g] != 0.0f) {
                const float4* ez = (const float4*)(pz + (b + g) * 16);
                float4 e0 = ez[0], e1 = ez[1], e2 = ez[2], e3 = ez[3];
                float w = exy[g];
                acc[0]  = fmaf(w, e0.x, acc[0]);
                acc[1]  = fmaf(w, e0.y, acc[1]);
                acc[2]  = fmaf(w, e0.z, acc[2]);
                acc[3]  = fmaf(w, e0.w, acc[3]);
                acc[4]  = fmaf(w, e1.x, acc[4]);
                acc[5]  = fmaf(w, e1.y, acc[5]);
                acc[6]  = fmaf(w, e1.z, acc[6]);
                acc[7]  = fmaf(w, e1.w, acc[7]);
                acc[8]  = fmaf(w, e2.x, acc[8]);
                acc[9]  = fmaf(w, e2.y, acc[9]);
                acc[10] = fmaf(w, e2.z, acc[10]);
                acc[11] = fmaf(w, e2.w, acc[11]);
                acc[12] = fmaf(w, e3.x, acc[12]);
                acc[13] = fmaf(w, e3.y, acc[13]);
                acc[14] = fmaf(w, e3.z, acc[14]);
                acc[15] = fmaf(w, e3.w, acc[15]);
            }
        }
    }

    // Transposed writeout (stage aliases px/py region): coalesced float4 stores.
    __syncthreads();
    float* stage = &buf[SM_STAGE];
#pragma unroll
    for (int z = 0; z < 16; z++) stage[z * 256 + tid] = acc[z];
    __syncthreads();

#pragma unroll
    for (int s = 0; s < 4; s++) {
        int idx = s * 256 + tid;
        int f   = idx << 2;
        int c   = f >> 4;
        int z0  = f & 15;
        float4 v;
        v.x = stage[(z0 + 0) * 256 + c];
        v.y = stage[(z0 + 1) * 256 + c];
        v.z = stage[(z0 + 2) * 256 + c];
        v.w = stage[(z0 + 3) * 256 + c];
        int addr = (ox + (c >> 4)) * 65536 + (oy + (c & 15)) * 256 + oz + z0;
        *(float4*)&out[addr] = v;
    }
}

extern "C" void kernel_launch(void* const* d_in, const int* in_sizes, int n_in,
                              void* d_out, int out_size) {
    const float* centers = (const float*)d_in[0];
    const float* sigmas = (const float*)d_in[1];
    const float* intensities = (const float*)d_in[2];
    float* out = (float*)d_out;
    const int n = in_sizes[1];

    void* counts_ptr = nullptr;
    cudaGetSymbolAddress(&counts_ptr, d_counts);
    cudaMemsetAsync(counts_ptr, 0, NTILES * sizeof(int), 0);

    scatter_kernel<<<(n + 255) / 256, 256>>>(centers, sigmas, intensities, n);
    accum_kernel<<<NTILES, 256>>>(out);
}

// round 8
// speedup vs baseline: 1.3303x; 1.0222x over previous
#include <cuda_runtime.h>

// Gaussian splatting via fine-grained tile-owned gather (8^3 subtiles).
// memset node: zero per-tile counters. K2: per-gaussian param prep + bucket
// scatter. K3: one 64-thread CTA per 8^3 tile; thread owns an (x,y) column of
// 8 z-voxels in registers; per-tile exp tables built once in smem (single
// barrier), scalar scan over the short gaussian list; volume written exactly
// once with float4 stores.

#define NT 32                           // tiles per axis (256/8)
#define NTILES (NT * NT * NT)           // 32768
#define TS 8
#define CAP 64
#define NMAX 65536

__device__ int    d_counts[NTILES];
__device__ int    d_bucket[NTILES * CAP];
__device__ float4 d_params[2 * NMAX];   // [2g]={cx,cy,cz,inv2s2}; [2g+1]={I, mnPack, mxm1Pack, 0}

__global__ void scatter_kernel(const float* __restrict__ centers,
                               const float* __restrict__ sigmas,
                               const float* __restrict__ intensities,
                               int n) {
    int g = blockIdx.x * blockDim.x + threadIdx.x;
    if (g >= n) return;

    float c3[3];
    c3[0] = __ldg(&centers[3 * g + 0]);
    c3[1] = __ldg(&centers[3 * g + 1]);
    c3[2] = __ldg(&centers[3 * g + 2]);
    const float sig   = __ldg(&sigmas[g]);
    const float inten = __ldg(&intensities[g]);

    const float cut    = 3.0f * sig * 255.0f;
    const float inv2s2 = 0.5f / (sig * sig);

    int mn[3], mx[3];
#pragma unroll
    for (int a = 0; a < 3; a++) {
        float cv = c3[a] * 255.0f;
        mn[a] = (int)floorf(fmaxf(cv - cut, 0.0f));
        mx[a] = (int)fminf(floorf(fminf(cv + cut, 255.0f)) + 1.0f, 256.0f);
    }

    unsigned mnp = (unsigned)mn[0] | ((unsigned)mn[1] << 8) | ((unsigned)mn[2] << 16);
    unsigned mxp = (unsigned)(mx[0] - 1) | ((unsigned)(mx[1] - 1) << 8) | ((unsigned)(mx[2] - 1) << 16);

    d_params[2 * g + 0] = make_float4(c3[0], c3[1], c3[2], inv2s2);
    d_params[2 * g + 1] = make_float4(inten, __uint_as_float(mnp), __uint_as_float(mxp), 0.0f);

    const int t0x = mn[0] >> 3, t1x = (mx[0] - 1) >> 3;
    const int t0y = mn[1] >> 3, t1y = (mx[1] - 1) >> 3;
    const int t0z = mn[2] >> 3, t1z = (mx[2] - 1) >> 3;

    for (int tx = t0x; tx <= t1x; tx++)
        for (int ty = t0y; ty <= t1y; ty++)
            for (int tz = t0z; tz <= t1z; tz++) {
                int t = (tx << 10) | (ty << 5) | tz;
                int slot = atomicAdd(&d_counts[t], 1);
                if (slot < CAP) d_bucket[t * CAP + slot] = g;
            }
}

// Per-gaussian table block: 32 floats = [ex 0..8) [ey 8..16) [ez 16..24) pad.
__global__ void __launch_bounds__(64) accum_kernel(float* __restrict__ out) {
    const int t   = blockIdx.x;
    const int tid = threadIdx.x;
    const int ox = (t >> 10) << 3;
    const int oy = ((t >> 5) & 31) << 3;
    const int oz = (t & 31) << 3;

    __shared__ __align__(16) float4 par[CAP * 2];
    __shared__ __align__(16) float  tab[CAP * 32];

    int cnt = d_counts[t];
    if (cnt > CAP) cnt = CAP;
    const int bucket_base = t * CAP;

    // Stage params coalesced.
    for (int i = tid; i < cnt * 2; i += 64) {
        int g = i >> 1, h = i & 1;
        int gid = d_bucket[bucket_base + g];
        par[i] = d_params[2 * gid + h];
    }
    __syncthreads();

    // Build all tables (24 used slots per gaussian, stride 32).
    for (int e = tid; e < cnt * 32; e += 64) {
        int r = e & 31;
        if (r >= 24) continue;
        int g = e >> 5;
        int a = r >> 3, i = r & 7;
        float4 p0 = par[2 * g + 0];
        float4 p1 = par[2 * g + 1];
        float c = (a == 0) ? p0.x : ((a == 1) ? p0.y : p0.z);
        unsigned mnp = __float_as_uint(p1.y);
        unsigned mxp = __float_as_uint(p1.z);
        int mn_a = (int)((mnp >> (8 * a)) & 255u);
        int mx_a = (int)((mxp >> (8 * a)) & 255u);
        int o = (a == 0) ? ox : ((a == 1) ? oy : oz);
        int gi = o + i;
        float v = 0.0f;
        if (gi >= mn_a && gi <= mx_a) {
            float d = (float)gi / 255.0f - c;
            v = __expf(-d * d * p0.w);
            if (a == 2) v *= p1.x;
        }
        tab[g * 32 + a * 8 + i] = v;
    }
    __syncthreads();

    const int xi = tid >> 3;
    const int yi = tid & 7;

    float acc[8];
#pragma unroll
    for (int z = 0; z < 8; z++) acc[z] = 0.0f;

    // Scan the short list; z-table loads are two LDS.128 per active gaussian.
    for (int g = 0; g < cnt; g++) {
        const float* tg = &tab[g * 32];
        float exy = tg[xi] * tg[8 + yi];
        if (exy != 0.0f) {
            float4 e0 = *(const float4*)(tg + 16);
            float4 e1 = *(const float4*)(tg + 20);
            acc[0] = fmaf(exy, e0.x, acc[0]);
            acc[1] = fmaf(exy, e0.y, acc[1]);
            acc[2] = fmaf(exy, e0.z, acc[2]);
            acc[3] = fmaf(exy, e0.w, acc[3]);
            acc[4] = fmaf(exy, e1.x, acc[4]);
            acc[5] = fmaf(exy, e1.y, acc[5]);
            acc[6] = fmaf(exy, e1.z, acc[6]);
            acc[7] = fmaf(exy, e1.w, acc[7]);
        }
    }

    // Direct writeout: each thread stores its own 8-voxel z column.
    const int addr = (ox + xi) * 65536 + (oy + yi) * 256 + oz;
    *(float4*)&out[addr]     = make_float4(acc[0], acc[1], acc[2], acc[3]);
    *(float4*)&out[addr + 4] = make_float4(acc[4], acc[5], acc[6], acc[7]);
}

extern "C" void kernel_launch(void* const* d_in, const int* in_sizes, int n_in,
                              void* d_out, int out_size) {
    const float* centers = (const float*)d_in[0];
    const float* sigmas = (const float*)d_in[1];
    const float* intensities = (const float*)d_in[2];
    float* out = (float*)d_out;
    const int n = in_sizes[1];

    void* counts_ptr = nullptr;
    cudaGetSymbolAddress(&counts_ptr, d_counts);
    cudaMemsetAsync(counts_ptr, 0, NTILES * sizeof(int), 0);

    scatter_kernel<<<(n + 255) / 256, 256>>>(centers, sigmas, intensities, n);
    accum_kernel<<<NTILES, 64>>>(out);
}